// round 2
// baseline (speedup 1.0000x reference)
#include <cuda_runtime.h>
#include <math.h>

#define BATCH 2
#define CIN 256
#define COUT 256
#define HHI 256
#define WHI 512
#define HLO 128
#define WLO 256
#define MMAX 129
#define LMAX 128
#define CPG 8
#define BC (BATCH*CIN)          /* 512    */
#define ROWS1 (BC*HHI)          /* 131072 */
#define ROWS2 (BC*HLO)          /* 65536  */
#define HWLO (HLO*WLO)          /* 32768  */

// -------- scratch (static device globals; no allocation allowed) --------
__device__ float d_Xr[MMAX*ROWS1];        // [m][bc*256+kh]
__device__ float d_Xi[MMAX*ROWS1];
__device__ float d_A [MMAX*HHI*HLO];      // [m][kh][klo]
__device__ float d_Gr[MMAX*ROWS2];        // [m][bc*128+klo]
__device__ float d_Gi[MMAX*ROWS2];
__device__ float d_Y [BC*HWLO];           // [bc][klo*256+w]
__device__ float d_H [BC*HWLO];           // [b][o][hw]
__device__ float d_mean[BATCH*32];
__device__ float d_rstd[BATCH*32];

// ============================================================
// Stage 1: rfft(512) per row, scaled by 2*pi/512.
// Real-packed: z[n]=x[2n]+i x[2n+1], 256-pt complex FFT, untangle.
// 8 warps/block, 1 row/warp. Output transposed to [m][row] via smem staging.
// ============================================================
__global__ void k_fft_fwd(const float* __restrict__ x) {
    __shared__ float sre[8][256];
    __shared__ float sim[8][256];
    __shared__ float twr[128], twi[128];   // e^{-2pi i j/256}
    __shared__ float uer[129], uei[129];   // e^{-2pi i k/512}
    __shared__ float ore[129*8], oim[129*8];
    int tid = threadIdx.x;
    if (tid < 128) { float s,c; sincosf(-6.283185307179586f*(float)tid/256.0f,&s,&c); twr[tid]=c; twi[tid]=s; }
    if (tid < 129) { float s,c; sincosf(-6.283185307179586f*(float)tid/512.0f,&s,&c); uer[tid]=c; uei[tid]=s; }
    __syncthreads();
    int w = tid >> 5, lane = tid & 31;
    int row = blockIdx.x*8 + w;
    const float4* xr4 = (const float4*)(x + (size_t)row*512);
    #pragma unroll
    for (int j = 0; j < 4; j++) {
        float4 v = xr4[lane + 32*j];
        int f  = lane + 32*j;
        int r0 = __brev(2*f)   >> 24;
        int r1 = __brev(2*f+1) >> 24;
        sre[w][r0]=v.x; sim[w][r0]=v.y;
        sre[w][r1]=v.z; sim[w][r1]=v.w;
    }
    __syncwarp();
    for (int st = 0; st < 8; st++) {
        int half = 1 << st;
        int tstep = 128 >> st;               // 256/len
        #pragma unroll 4
        for (int b = lane; b < 128; b += 32) {
            int blk = b >> st;
            int j   = b & (half-1);
            int i0  = (blk << (st+1)) + j;
            int i1  = i0 + half;
            float wr = twr[j*tstep], wi = twi[j*tstep];
            float ur = sre[w][i0], ui = sim[w][i0];
            float vr = sre[w][i1], vi = sim[w][i1];
            float tr = vr*wr - vi*wi, ti = vr*wi + vi*wr;
            sre[w][i0]=ur+tr; sim[w][i0]=ui+ti;
            sre[w][i1]=ur-tr; sim[w][i1]=ui-ti;
        }
        __syncwarp();
    }
    const float SC = 0.012271846303085129f;  // 2*pi/512
    for (int k = lane; k < 129; k += 32) {
        int km = (256-k) & 255;
        float zr=sre[w][k],  zi= sim[w][k];
        float mr=sre[w][km], mi=-sim[w][km];
        float er=0.5f*(zr+mr), ei=0.5f*(zi+mi);
        float dr=0.5f*(zr-mr), di=0.5f*(zi-mi);
        float pr=di, pi=-dr;                  // -i * d
        float wr=uer[k], wi=uei[k];
        float qr=pr*wr-pi*wi, qi=pr*wi+pi*wr;
        ore[k*8+w] = (er+qr)*SC;
        oim[k*8+w] = (ei+qi)*SC;
    }
    __syncthreads();
    int base = blockIdx.x*8;
    for (int idx = tid; idx < 129*8; idx += 256) {
        int m = idx >> 3, r = idx & 7;
        d_Xr[m*ROWS1 + base + r] = ore[idx];
        d_Xi[m*ROWS1 + base + r] = oim[idx];
    }
}

// ============================================================
// Stage 2: A[m][kh][klo] = sum_l wmat[m][l][kh] * pct[m][l][klo]
// Tiled GEMM 64x64, K=128.
// ============================================================
__global__ void k_buildA(const float* __restrict__ wmat, const float* __restrict__ pct) {
    int m    = blockIdx.z;
    int kh0  = blockIdx.x * 64;
    int klo0 = blockIdx.y * 64;
    __shared__ float sW[16][65];  // [l][kh]
    __shared__ float sP[16][64];  // [l][klo]
    int tid = threadIdx.x;
    int tx = tid & 15, ty = tid >> 4;
    float acc[4][4] = {};
    const float* wbase = wmat + m*LMAX*HHI;
    const float* pbase = pct  + m*LMAX*HLO;
    for (int l0 = 0; l0 < 128; l0 += 16) {
        #pragma unroll
        for (int q = 0; q < 4; q++) {
            int e = tid + q*256;
            int li = e >> 6, ki = e & 63;
            sW[li][ki] = wbase[(l0+li)*HHI + kh0  + ki];
            sP[li][ki] = pbase[(l0+li)*HLO + klo0 + ki];
        }
        __syncthreads();
        #pragma unroll
        for (int l = 0; l < 16; l++) {
            float a[4], b[4];
            #pragma unroll
            for (int i=0;i<4;i++) a[i]=sW[l][ty*4+i];
            #pragma unroll
            for (int j=0;j<4;j++) b[j]=sP[l][tx*4+j];
            #pragma unroll
            for (int i=0;i<4;i++)
                #pragma unroll
                for (int j=0;j<4;j++) acc[i][j] += a[i]*b[j];
        }
        __syncthreads();
    }
    float* Ab = d_A + m*HHI*HLO;
    #pragma unroll
    for (int i=0;i<4;i++)
        #pragma unroll
        for (int j=0;j<4;j++)
            Ab[(kh0+ty*4+i)*HLO + klo0 + tx*4 + j] = acc[i][j];
}

// ============================================================
// Stage 3: per-m GEMM, real & imag share the A tile.
// G_m[512,128] = X_m[512,256] @ A_m[256,128]
// ============================================================
__global__ void k_legendre() {
    int m    = blockIdx.z;
    int bc0  = blockIdx.x * 64;
    int klo0 = blockIdx.y * 64;
    __shared__ float sXr[16][65], sXi[16][65];  // [k][bc]
    __shared__ float sA[16][64];                // [k][klo]
    int tid = threadIdx.x, tx = tid & 15, ty = tid >> 4;
    float accR[4][4] = {}, accI[4][4] = {};
    const float* Xr = d_Xr + m*ROWS1 + bc0*HHI;
    const float* Xi = d_Xi + m*ROWS1 + bc0*HHI;
    const float* Ab = d_A  + m*HHI*HLO;
    for (int k0 = 0; k0 < 256; k0 += 16) {
        #pragma unroll
        for (int q = 0; q < 4; q++) {
            int e = tid + q*256;
            int bi = e >> 4, ki = e & 15;
            sXr[ki][bi] = Xr[bi*HHI + k0 + ki];
            sXi[ki][bi] = Xi[bi*HHI + k0 + ki];
        }
        #pragma unroll
        for (int q = 0; q < 4; q++) {
            int e = tid + q*256;
            int ki = e >> 6, ji = e & 63;
            sA[ki][ji] = Ab[(k0+ki)*HLO + klo0 + ji];
        }
        __syncthreads();
        #pragma unroll
        for (int k = 0; k < 16; k++) {
            float a[4], xr[4], xi[4];
            #pragma unroll
            for (int j=0;j<4;j++) a[j]=sA[k][tx*4+j];
            #pragma unroll
            for (int i=0;i<4;i++){ xr[i]=sXr[k][ty*4+i]; xi[i]=sXi[k][ty*4+i]; }
            #pragma unroll
            for (int i=0;i<4;i++)
                #pragma unroll
                for (int j=0;j<4;j++){ accR[i][j]+=xr[i]*a[j]; accI[i][j]+=xi[i]*a[j]; }
        }
        __syncthreads();
    }
    float* Gr = d_Gr + m*ROWS2;
    float* Gi = d_Gi + m*ROWS2;
    #pragma unroll
    for (int i=0;i<4;i++)
        #pragma unroll
        for (int j=0;j<4;j++) {
            int r = bc0+ty*4+i, c = klo0+tx*4+j;
            Gr[r*HLO + c] = accR[i][j];
            Gi[r*HLO + c] = accI[i][j];
        }
}

// ============================================================
// Stage 4: irfft(n=256) * 256 per row via packed 128-pt inverse FFT.
// Z[k] = X[k]*(1 + i w_k) + conj(X[128-k])*(1 - i w_k),  w_k = e^{+2pi i k/256}
// z[n] = sum Z[k] e^{+2pi i k n/128};  y[2n]=Re z, y[2n+1]=Im z.
// ============================================================
__global__ void k_ifft() {
    __shared__ float gre[129*8], gim[129*8];
    __shared__ float sre[8][128], sim[8][128];
    __shared__ float wqr[128], wqi[128];  // e^{+2pi i k/256}
    __shared__ float t2r[64],  t2i[64];   // e^{+2pi i j/128}
    int tid = threadIdx.x;
    if (tid < 128){ float s,c; sincosf(6.283185307179586f*(float)tid/256.f,&s,&c); wqr[tid]=c; wqi[tid]=s; }
    if (tid < 64 ){ float s,c; sincosf(6.283185307179586f*(float)tid/128.f,&s,&c); t2r[tid]=c; t2i[tid]=s; }
    int base = blockIdx.x*8;
    for (int idx = tid; idx < 129*8; idx += 256) {
        int m = idx >> 3, r = idx & 7;
        gre[idx] = d_Gr[m*ROWS2 + base + r];
        gim[idx] = d_Gi[m*ROWS2 + base + r];
    }
    __syncthreads();
    int w = tid >> 5, lane = tid & 31;
    #pragma unroll 4
    for (int k = lane; k < 128; k += 32) {
        float ar = gre[k*8+w],        ai =  gim[k*8+w];
        float br = gre[(128-k)*8+w],  bi = -gim[(128-k)*8+w];
        float wr = wqr[k], wi = wqi[k];
        float c1r = 1.f - wi, c1i =  wr;
        float c2r = 1.f + wi, c2i = -wr;
        float Zr = ar*c1r - ai*c1i + br*c2r - bi*c2i;
        float Zi = ar*c1i + ai*c1r + br*c2i + bi*c2r;
        int rv = __brev(k) >> 25;
        sre[w][rv] = Zr; sim[w][rv] = Zi;
    }
    __syncwarp();
    for (int st = 0; st < 7; st++) {
        int half = 1 << st;
        int tstep = 64 >> st;                 // 128/len
        #pragma unroll 2
        for (int b = lane; b < 64; b += 32) {
            int blk = b >> st;
            int j   = b & (half-1);
            int i0  = (blk << (st+1)) + j;
            int i1  = i0 + half;
            float wr = t2r[j*tstep], wi = t2i[j*tstep];
            float ur = sre[w][i0], ui = sim[w][i0];
            float vr = sre[w][i1], vi = sim[w][i1];
            float tr = vr*wr - vi*wi, ti = vr*wi + vi*wr;
            sre[w][i0]=ur+tr; sim[w][i0]=ui+ti;
            sre[w][i1]=ur-tr; sim[w][i1]=ui-ti;
        }
        __syncwarp();
    }
    float2* yo = (float2*)d_Y + (size_t)(base + w)*128;
    #pragma unroll 4
    for (int n = lane; n < 128; n += 32)
        yo[n] = make_float2(sre[w][n], sim[w][n]);
}

// ============================================================
// Stage 5: 1x1 conv = per-batch GEMM h[o,n] = W[o,c] y[c,n] + bias[o]
// ============================================================
__global__ void k_conv(const float* __restrict__ wgt, const float* __restrict__ bias) {
    int b  = blockIdx.z;
    int o0 = blockIdx.y * 64;
    int n0 = blockIdx.x * 64;
    __shared__ float sW[16][65];  // [c][o]
    __shared__ float sY[16][64];  // [c][n]
    int tid = threadIdx.x, tx = tid & 15, ty = tid >> 4;
    float acc[4][4] = {};
    const float* Yb = d_Y + b*CIN*HWLO;
    for (int c0 = 0; c0 < 256; c0 += 16) {
        #pragma unroll
        for (int q = 0; q < 4; q++) {
            int e = tid + q*256;
            int oi = e >> 4, ci = e & 15;
            sW[ci][oi] = wgt[(o0+oi)*CIN + c0 + ci];
        }
        #pragma unroll
        for (int q = 0; q < 4; q++) {
            int e = tid + q*256;
            int ci = e >> 6, ni = e & 63;
            sY[ci][ni] = Yb[(c0+ci)*HWLO + n0 + ni];
        }
        __syncthreads();
        #pragma unroll
        for (int k = 0; k < 16; k++) {
            float a[4], y[4];
            #pragma unroll
            for (int i=0;i<4;i++) a[i]=sW[k][ty*4+i];
            #pragma unroll
            for (int j=0;j<4;j++) y[j]=sY[k][tx*4+j];
            #pragma unroll
            for (int i=0;i<4;i++)
                #pragma unroll
                for (int j=0;j<4;j++) acc[i][j] += a[i]*y[j];
        }
        __syncthreads();
    }
    float* Hb = d_H + b*COUT*HWLO;
    #pragma unroll
    for (int i=0;i<4;i++) {
        float bi_ = bias[o0+ty*4+i];
        #pragma unroll
        for (int j=0;j<4;j++)
            Hb[(o0+ty*4+i)*HWLO + n0 + tx*4 + j] = acc[i][j] + bi_;
    }
}

// ============================================================
// Stage 6: GroupNorm stats (deterministic, double accumulators)
// ============================================================
__global__ void k_gnstat() {
    int bg = blockIdx.x;                       // b*32 + g, slabs contiguous
    const float* hb = d_H + (size_t)bg * (CPG*HWLO);
    const int N = CPG*HWLO;                    // 262144
    double s = 0.0, s2 = 0.0;
    for (int i = threadIdx.x; i < N; i += 256) {
        float v = hb[i];
        s += (double)v; s2 += (double)v*(double)v;
    }
    __shared__ double sh[256], sh2[256];
    sh[threadIdx.x] = s; sh2[threadIdx.x] = s2;
    __syncthreads();
    for (int st = 128; st > 0; st >>= 1) {
        if (threadIdx.x < st) { sh[threadIdx.x] += sh[threadIdx.x+st]; sh2[threadIdx.x] += sh2[threadIdx.x+st]; }
        __syncthreads();
    }
    if (threadIdx.x == 0) {
        double mean = sh[0] / N;
        double var  = sh2[0] / N - mean*mean;
        d_mean[bg] = (float)mean;
        d_rstd[bg] = rsqrtf((float)var + 1e-5f);
    }
}

// ============================================================
// Stage 7: normalize + affine + exact GELU (x * Phi(x))
// ============================================================
__global__ void k_gnapply(const float* __restrict__ gamma, const float* __restrict__ beta,
                          float* __restrict__ out) {
    int idx = blockIdx.x*256 + threadIdx.x;    // float4 index; grid exactly covers
    int fidx = idx * 4;
    int o  = (fidx >> 15) & 255;
    int bg = fidx >> 18;
    float a  = gamma[o] * d_rstd[bg];
    float b2 = beta[o] - d_mean[bg] * a;
    float4 h = ((const float4*)d_H)[idx];
    float v0 = h.x*a + b2, v1 = h.y*a + b2, v2 = h.z*a + b2, v3 = h.w*a + b2;
    float4 r;
    r.x = v0 * normcdff(v0);
    r.y = v1 * normcdff(v1);
    r.z = v2 * normcdff(v2);
    r.w = v3 * normcdff(v3);
    ((float4*)out)[idx] = r;
}

// ============================================================
extern "C" void kernel_launch(void* const* d_in, const int* in_sizes, int n_in,
                              void* d_out, int out_size) {
    const float* x      = (const float*)d_in[0];
    const float* conv_w = (const float*)d_in[1];
    const float* conv_b = (const float*)d_in[2];
    const float* gamma  = (const float*)d_in[3];
    const float* beta   = (const float*)d_in[4];
    const float* wmat   = (const float*)d_in[5];
    const float* pct    = (const float*)d_in[6];
    float* out = (float*)d_out;

    k_fft_fwd <<<ROWS1/8, 256>>>(x);
    k_buildA  <<<dim3(4,2,MMAX), 256>>>(wmat, pct);
    k_legendre<<<dim3(8,2,MMAX), 256>>>();
    k_ifft    <<<ROWS2/8, 256>>>();
    k_conv    <<<dim3(HWLO/64, COUT/64, BATCH), 256>>>(conv_w, conv_b);
    k_gnstat  <<<BATCH*32, 256>>>();
    k_gnapply <<<(BC*HWLO)/4/256, 256>>>(gamma, beta, out);
}

// round 4
// speedup vs baseline: 1.2876x; 1.2876x over previous
#include <cuda_runtime.h>
#include <cuda_bf16.h>
#include <math.h>
#include <stdint.h>

#define BATCH 2
#define CIN 256
#define COUT 256
#define HHI 256
#define WHI 512
#define HLO 128
#define WLO 256
#define MMAX 129
#define LMAX 128
#define CPG 8
#define BC (BATCH*CIN)          /* 512    */
#define ROWS1 (BC*HHI)          /* 131072 */
#define ROWS2 (BC*HLO)          /* 65536  */
#define HWLO (HLO*WLO)          /* 32768  */

// -------- scratch (static device globals; no allocation allowed) --------
__device__ __align__(16) __nv_bfloat16 d_Xr_hi[MMAX*ROWS1];
__device__ __align__(16) __nv_bfloat16 d_Xr_lo[MMAX*ROWS1];
__device__ __align__(16) __nv_bfloat16 d_Xi_hi[MMAX*ROWS1];
__device__ __align__(16) __nv_bfloat16 d_Xi_lo[MMAX*ROWS1];
__device__ __align__(16) __nv_bfloat16 d_At_hi[MMAX*HLO*HHI];   // [m][klo][kh]
__device__ __align__(16) __nv_bfloat16 d_At_lo[MMAX*HLO*HHI];
__device__ __align__(16) __nv_bfloat16 d_Whi[COUT*CIN];
__device__ __align__(16) __nv_bfloat16 d_Wlo[COUT*CIN];
__device__ float d_Gr[MMAX*ROWS2];        // [m][bc*128+klo]
__device__ float d_Gi[MMAX*ROWS2];
__device__ float d_Y [BC*HWLO];           // [b][c][hw]
__device__ __align__(16) __nv_bfloat16 d_Yt_hi[BATCH*HWLO*CIN]; // [b][hw][c]
__device__ __align__(16) __nv_bfloat16 d_Yt_lo[BATCH*HWLO*CIN];
__device__ float d_H [BC*HWLO];           // [b][o][hw]
__device__ double d_ps[512], d_ps2[512];
__device__ float d_mean[BATCH*32];
__device__ float d_rstd[BATCH*32];

// ======================= helpers =======================
__device__ __forceinline__ uint32_t smem_u32(const void* p) {
    uint32_t a;
    asm("{ .reg .u64 t; cvta.to.shared.u64 t, %1; cvt.u32.u64 %0, t; }" : "=r"(a) : "l"(p));
    return a;
}
__device__ __forceinline__ void ldsm_x4(uint32_t& r0, uint32_t& r1, uint32_t& r2, uint32_t& r3, uint32_t addr) {
    asm volatile("ldmatrix.sync.aligned.m8n8.x4.shared.b16 {%0,%1,%2,%3}, [%4];"
        : "=r"(r0), "=r"(r1), "=r"(r2), "=r"(r3) : "r"(addr));
}
__device__ __forceinline__ void mma16816(float* d, const uint32_t* a, uint32_t b0, uint32_t b1) {
    asm volatile("mma.sync.aligned.m16n8k16.row.col.f32.bf16.bf16.f32 "
        "{%0,%1,%2,%3}, {%4,%5,%6,%7}, {%8,%9}, {%0,%1,%2,%3};"
        : "+f"(d[0]), "+f"(d[1]), "+f"(d[2]), "+f"(d[3])
        : "r"(a[0]), "r"(a[1]), "r"(a[2]), "r"(a[3]), "r"(b0), "r"(b1));
}
__device__ __forceinline__ void split2(float v, __nv_bfloat16& h, __nv_bfloat16& l) {
    h = __float2bfloat16(v);
    l = __float2bfloat16(v - __bfloat162float(h));
}

// ============================================================
// Shared 128x128 GEMM core, K=256, bf16 hi/lo 3-term split, fp32 accum.
// A[128][256] row-major (k-major), B[128][256] row-major (n rows, k-major).
// D[r][c] (ldD stride) = sum_k A[r][k]*B[c][k]  (+ bias[r]).
// 256 threads: warp grid 4(m) x 2(n), warp tile 32x64.
// ============================================================
__device__ __forceinline__ void gemm_core(
    const __nv_bfloat16* __restrict__ Ahi, const __nv_bfloat16* __restrict__ Alo,
    const __nv_bfloat16* __restrict__ Bhi, const __nv_bfloat16* __restrict__ Blo,
    float* __restrict__ D, int ldD, const float* __restrict__ bias)
{
    __shared__ __align__(128) __nv_bfloat16 sA[128*64];
    __shared__ __align__(128) __nv_bfloat16 sB[128*64];
    int tid = threadIdx.x;
    int wid = tid >> 5, lane = tid & 31;
    int wm = wid >> 1, wn = wid & 1;
    uint32_t sA32 = smem_u32(sA), sB32 = smem_u32(sB);

    float acc[2][8][4];
    #pragma unroll
    for (int i=0;i<2;i++)
        #pragma unroll
        for (int j=0;j<8;j++)
            #pragma unroll
            for (int q=0;q<4;q++) acc[i][j][q] = 0.f;

    #pragma unroll 1
    for (int t = 0; t < 3; t++) {
        const __nv_bfloat16* Ap = (t==1) ? Alo : Ahi;
        const __nv_bfloat16* Bp = (t==2) ? Blo : Bhi;
        #pragma unroll 1
        for (int kc = 0; kc < 4; kc++) {
            __syncthreads();
            #pragma unroll
            for (int e = tid; e < 1024; e += 256) {
                int row = e >> 3, c = e & 7;
                uint32_t off = (uint32_t)(row << 7) + (uint32_t)((c ^ (row & 7)) << 4);
                uint4 va = *(const uint4*)(Ap + (size_t)row*256 + kc*64 + c*8);
                *(uint4*)((char*)sA + off) = va;
                uint4 vb = *(const uint4*)(Bp + (size_t)row*256 + kc*64 + c*8);
                *(uint4*)((char*)sB + off) = vb;
            }
            __syncthreads();
            #pragma unroll
            for (int ks = 0; ks < 4; ks++) {
                uint32_t a[2][4];
                #pragma unroll
                for (int mi = 0; mi < 2; mi++) {
                    int row = wm*32 + mi*16 + (lane & 15);
                    int c   = ks*2 + (lane >> 4);
                    uint32_t addr = sA32 + (uint32_t)(row << 7) + (uint32_t)(((c ^ (row & 7))) << 4);
                    ldsm_x4(a[mi][0], a[mi][1], a[mi][2], a[mi][3], addr);
                }
                uint32_t b[4][4];
                #pragma unroll
                for (int nj = 0; nj < 4; nj++) {
                    int row = wn*64 + nj*16 + (lane & 7) + ((lane >> 3) & 1)*8;
                    int c   = ks*2 + (lane >> 4);
                    uint32_t addr = sB32 + (uint32_t)(row << 7) + (uint32_t)(((c ^ (row & 7))) << 4);
                    ldsm_x4(b[nj][0], b[nj][1], b[nj][2], b[nj][3], addr);
                }
                #pragma unroll
                for (int mi = 0; mi < 2; mi++)
                    #pragma unroll
                    for (int nj = 0; nj < 4; nj++) {
                        mma16816(acc[mi][nj*2],   a[mi], b[nj][0], b[nj][2]);
                        mma16816(acc[mi][nj*2+1], a[mi], b[nj][1], b[nj][3]);
                    }
            }
        }
    }

    int g = lane >> 2, tg = lane & 3;
    #pragma unroll
    for (int mi = 0; mi < 2; mi++) {
        int r0 = wm*32 + mi*16 + g;
        float bv0 = bias ? bias[r0]   : 0.f;
        float bv1 = bias ? bias[r0+8] : 0.f;
        #pragma unroll
        for (int nt = 0; nt < 8; nt++) {
            int col = wn*64 + nt*8 + tg*2;
            float2 v0 = make_float2(acc[mi][nt][0] + bv0, acc[mi][nt][1] + bv0);
            float2 v1 = make_float2(acc[mi][nt][2] + bv1, acc[mi][nt][3] + bv1);
            *(float2*)&D[(size_t)r0*ldD + col]     = v0;
            *(float2*)&D[(size_t)(r0+8)*ldD + col] = v1;
        }
    }
}

// ============================================================
// Stage 1: rfft(512) per row, scaled by 2*pi/512. Output bf16 hi/lo, [m][row].
// ============================================================
__global__ void k_fft_fwd(const float* __restrict__ x) {
    __shared__ float sre[8][256];
    __shared__ float sim[8][256];
    __shared__ float twr[128], twi[128];
    __shared__ float uer[129], uei[129];
    __shared__ float ore[129*8], oim[129*8];
    int tid = threadIdx.x;
    if (tid < 128) { float s,c; sincosf(-6.283185307179586f*(float)tid/256.0f,&s,&c); twr[tid]=c; twi[tid]=s; }
    if (tid < 129) { float s,c; sincosf(-6.283185307179586f*(float)tid/512.0f,&s,&c); uer[tid]=c; uei[tid]=s; }
    __syncthreads();
    int w = tid >> 5, lane = tid & 31;
    int row = blockIdx.x*8 + w;
    const float4* xr4 = (const float4*)(x + (size_t)row*512);
    #pragma unroll
    for (int j = 0; j < 4; j++) {
        float4 v = xr4[lane + 32*j];
        int f  = lane + 32*j;
        int r0 = __brev(2*f)   >> 24;
        int r1 = __brev(2*f+1) >> 24;
        sre[w][r0]=v.x; sim[w][r0]=v.y;
        sre[w][r1]=v.z; sim[w][r1]=v.w;
    }
    __syncwarp();
    for (int st = 0; st < 8; st++) {
        int half = 1 << st;
        int tstep = 128 >> st;
        #pragma unroll 4
        for (int b = lane; b < 128; b += 32) {
            int blk = b >> st;
            int j   = b & (half-1);
            int i0  = (blk << (st+1)) + j;
            int i1  = i0 + half;
            float wr = twr[j*tstep], wi = twi[j*tstep];
            float ur = sre[w][i0], ui = sim[w][i0];
            float vr = sre[w][i1], vi = sim[w][i1];
            float tr = vr*wr - vi*wi, ti = vr*wi + vi*wr;
            sre[w][i0]=ur+tr; sim[w][i0]=ui+ti;
            sre[w][i1]=ur-tr; sim[w][i1]=ui-ti;
        }
        __syncwarp();
    }
    const float SC = 0.012271846303085129f;  // 2*pi/512
    for (int k = lane; k < 129; k += 32) {
        int km = (256-k) & 255;
        float zr=sre[w][k],  zi= sim[w][k];
        float mr=sre[w][km], mi=-sim[w][km];
        float er=0.5f*(zr+mr), ei=0.5f*(zi+mi);
        float dr=0.5f*(zr-mr), di=0.5f*(zi-mi);
        float pr=di, pi=-dr;
        float wr=uer[k], wi=uei[k];
        float qr=pr*wr-pi*wi, qi=pr*wi+pi*wr;
        ore[k*8+w] = (er+qr)*SC;
        oim[k*8+w] = (ei+qi)*SC;
    }
    __syncthreads();
    int base = blockIdx.x*8;
    for (int idx = tid; idx < 129*8; idx += 256) {
        int m = idx >> 3, r = idx & 7;
        size_t o = (size_t)m*ROWS1 + base + r;
        __nv_bfloat16 h, l;
        split2(ore[idx], h, l); d_Xr_hi[o]=h; d_Xr_lo[o]=l;
        split2(oim[idx], h, l); d_Xi_hi[o]=h; d_Xi_lo[o]=l;
    }
}

// ============================================================
// Stage 2: At[m][klo][kh] = sum_l wmat[m][l][kh]*pct[m][l][klo], bf16 hi/lo.
// ============================================================
__global__ void k_buildA(const float* __restrict__ wmat, const float* __restrict__ pct) {
    int m    = blockIdx.z;
    int kh0  = blockIdx.x * 64;
    int klo0 = blockIdx.y * 64;
    __shared__ float sW[16][65];
    __shared__ float sP[16][64];
    int tid = threadIdx.x;
    int tx = tid & 15, ty = tid >> 4;
    float acc[4][4] = {};
    const float* wbase = wmat + m*LMAX*HHI;
    const float* pbase = pct  + m*LMAX*HLO;
    for (int l0 = 0; l0 < 128; l0 += 16) {
        #pragma unroll
        for (int q = 0; q < 4; q++) {
            int e = tid + q*256;
            int li = e >> 6, ki = e & 63;
            sW[li][ki] = wbase[(l0+li)*HHI + kh0  + ki];
            sP[li][ki] = pbase[(l0+li)*HLO + klo0 + ki];
        }
        __syncthreads();
        #pragma unroll
        for (int l = 0; l < 16; l++) {
            float a[4], b[4];
            #pragma unroll
            for (int i=0;i<4;i++) a[i]=sW[l][ty*4+i];
            #pragma unroll
            for (int j=0;j<4;j++) b[j]=sP[l][tx*4+j];
            #pragma unroll
            for (int i=0;i<4;i++)
                #pragma unroll
                for (int j=0;j<4;j++) acc[i][j] += a[i]*b[j];
        }
        __syncthreads();
    }
    size_t Abase = (size_t)m*(HLO*HHI);
    #pragma unroll
    for (int j=0;j<4;j++) {
        int klo = klo0 + tx*4 + j;
        __nv_bfloat162 ph0, ph1, pl0, pl1;
        __nv_bfloat16 h, l;
        split2(acc[0][j], h, l); ph0.x=h; pl0.x=l;
        split2(acc[1][j], h, l); ph0.y=h; pl0.y=l;
        split2(acc[2][j], h, l); ph1.x=h; pl1.x=l;
        split2(acc[3][j], h, l); ph1.y=h; pl1.y=l;
        size_t o = Abase + (size_t)klo*HHI + kh0 + ty*4;
        *(__nv_bfloat162*)&d_At_hi[o]   = ph0;
        *(__nv_bfloat162*)&d_At_hi[o+2] = ph1;
        *(__nv_bfloat162*)&d_At_lo[o]   = pl0;
        *(__nv_bfloat162*)&d_At_lo[o+2] = pl1;
    }
}

// ============================================================
// Stage 2b: split conv weights to bf16 hi/lo
// ============================================================
__global__ void k_wsplit(const float* __restrict__ w) {
    int i = blockIdx.x*256 + threadIdx.x;   // 65536 total
    __nv_bfloat16 h, l;
    split2(w[i], h, l);
    d_Whi[i] = h; d_Wlo[i] = l;
}

// ============================================================
// Stage 3: Legendre per-m GEMM via mma.sync.
// blockIdx.x in 0..7: [0..3]=real bc-tiles, [4..7]=imag bc-tiles. blockIdx.y = m.
// ============================================================
__global__ void __launch_bounds__(256) k_legendre_mma() {
    int m = blockIdx.y;
    int bx = blockIdx.x;
    int half = bx >> 2;
    int bc0  = (bx & 3) * 128;
    size_t xo = (size_t)m*ROWS1 + (size_t)bc0*HHI;
    const __nv_bfloat16 *Ah, *Al;
    float* D;
    if (half) { Ah = d_Xi_hi + xo; Al = d_Xi_lo + xo; D = d_Gi; }
    else      { Ah = d_Xr_hi + xo; Al = d_Xr_lo + xo; D = d_Gr; }
    D += (size_t)m*ROWS2 + (size_t)bc0*HLO;
    const __nv_bfloat16* Bh = d_At_hi + (size_t)m*(HLO*HHI);
    const __nv_bfloat16* Bl = d_At_lo + (size_t)m*(HLO*HHI);
    gemm_core(Ah, Al, Bh, Bl, D, HLO, nullptr);
}

// ============================================================
// Stage 4: irfft(n=256)*256 per row (packed 128-pt inverse FFT).
// ============================================================
__global__ void k_ifft() {
    __shared__ float gre[129*8], gim[129*8];
    __shared__ float sre[8][128], sim[8][128];
    __shared__ float wqr[128], wqi[128];
    __shared__ float t2r[64],  t2i[64];
    int tid = threadIdx.x;
    if (tid < 128){ float s,c; sincosf(6.283185307179586f*(float)tid/256.f,&s,&c); wqr[tid]=c; wqi[tid]=s; }
    if (tid < 64 ){ float s,c; sincosf(6.283185307179586f*(float)tid/128.f,&s,&c); t2r[tid]=c; t2i[tid]=s; }
    int base = blockIdx.x*8;
    for (int idx = tid; idx < 129*8; idx += 256) {
        int m = idx >> 3, r = idx & 7;
        gre[idx] = d_Gr[m*ROWS2 + base + r];
        gim[idx] = d_Gi[m*ROWS2 + base + r];
    }
    __syncthreads();
    int w = tid >> 5, lane = tid & 31;
    #pragma unroll 4
    for (int k = lane; k < 128; k += 32) {
        float ar = gre[k*8+w],        ai =  gim[k*8+w];
        float br = gre[(128-k)*8+w],  bi = -gim[(128-k)*8+w];
        float wr = wqr[k], wi = wqi[k];
        float c1r = 1.f - wi, c1i =  wr;
        float c2r = 1.f + wi, c2i = -wr;
        float Zr = ar*c1r - ai*c1i + br*c2r - bi*c2i;
        float Zi = ar*c1i + ai*c1r + br*c2i + bi*c2r;
        int rv = __brev(k) >> 25;
        sre[w][rv] = Zr; sim[w][rv] = Zi;
    }
    __syncwarp();
    for (int st = 0; st < 7; st++) {
        int half = 1 << st;
        int tstep = 64 >> st;
        #pragma unroll 2
        for (int b = lane; b < 64; b += 32) {
            int blk = b >> st;
            int j   = b & (half-1);
            int i0  = (blk << (st+1)) + j;
            int i1  = i0 + half;
            float wr = t2r[j*tstep], wi = t2i[j*tstep];
            float ur = sre[w][i0], ui = sim[w][i0];
            float vr = sre[w][i1], vi = sim[w][i1];
            float tr = vr*wr - vi*wi, ti = vr*wi + vi*wr;
            sre[w][i0]=ur+tr; sim[w][i0]=ui+ti;
            sre[w][i1]=ur-tr; sim[w][i1]=ui-ti;
        }
        __syncwarp();
    }
    float2* yo = (float2*)d_Y + (size_t)(base + w)*128;
    #pragma unroll 4
    for (int n = lane; n < 128; n += 32)
        yo[n] = make_float2(sre[w][n], sim[w][n]);
}

// ============================================================
// Stage 4b: transpose Y [b][c][hw] -> Yt [b][hw][c] with bf16 split.
// ============================================================
__global__ void k_ytrans() {
    __shared__ float t[32][33];
    int b = blockIdx.z, c0 = blockIdx.y*32, hw0 = blockIdx.x*32;
    int tx = threadIdx.x & 31, ty = threadIdx.x >> 5;   // 256 threads: ty 0..7
    const float* Y = d_Y + (size_t)b*CIN*HWLO;
    #pragma unroll
    for (int q = 0; q < 4; q++) {
        int c = c0 + ty + q*8;
        t[ty + q*8][tx] = Y[(size_t)c*HWLO + hw0 + tx];
    }
    __syncthreads();
    #pragma unroll
    for (int q = 0; q < 4; q++) {
        int hw = hw0 + ty + q*8;
        float v = t[tx][ty + q*8];
        __nv_bfloat16 h, l; split2(v, h, l);
        size_t o = ((size_t)b*HWLO + hw)*CIN + c0 + tx;
        d_Yt_hi[o] = h; d_Yt_lo[o] = l;
    }
}

// ============================================================
// Stage 5: 1x1 conv via mma.sync. D[o][hw] = W[o][c] * Yt[hw][c]
// ============================================================
__global__ void __launch_bounds__(256) k_conv_mma(const float* __restrict__ bias) {
    int b = blockIdx.z, o0 = blockIdx.y*128, hw0 = blockIdx.x*128;
    const __nv_bfloat16* Ah = d_Whi + (size_t)o0*CIN;
    const __nv_bfloat16* Al = d_Wlo + (size_t)o0*CIN;
    const __nv_bfloat16* Bh = d_Yt_hi + ((size_t)b*HWLO + hw0)*CIN;
    const __nv_bfloat16* Bl = d_Yt_lo + ((size_t)b*HWLO + hw0)*CIN;
    float* D = d_H + ((size_t)b*COUT + o0)*HWLO + hw0;
    gemm_core(Ah, Al, Bh, Bl, D, HWLO, bias + o0);
}

// ============================================================
// Stage 6: GroupNorm stats — two-phase deterministic reduction.
// ============================================================
__global__ void k_gnstat1() {
    int blk = blockIdx.x;             // 512 = 64 groups * 8 parts
    int bg = blk >> 3, part = blk & 7;
    const float* hb = d_H + (size_t)bg*(CPG*HWLO) + part*32768;
    double s = 0.0, s2 = 0.0;
    for (int i = threadIdx.x; i < 32768; i += 256) {
        float v = hb[i];
        s += (double)v; s2 += (double)v*(double)v;
    }
    __shared__ double sh[256], sh2[256];
    sh[threadIdx.x] = s; sh2[threadIdx.x] = s2;
    __syncthreads();
    for (int st = 128; st > 0; st >>= 1) {
        if (threadIdx.x < st) { sh[threadIdx.x] += sh[threadIdx.x+st]; sh2[threadIdx.x] += sh2[threadIdx.x+st]; }
        __syncthreads();
    }
    if (threadIdx.x == 0) { d_ps[blk] = sh[0]; d_ps2[blk] = sh2[0]; }
}
__global__ void k_gnstat2() {
    int bg = threadIdx.x;             // 64 threads
    double s = 0.0, s2 = 0.0;
    #pragma unroll
    for (int p = 0; p < 8; p++) { s += d_ps[bg*8+p]; s2 += d_ps2[bg*8+p]; }
    const double N = (double)(CPG*HWLO);
    double mean = s / N;
    double var  = s2 / N - mean*mean;
    d_mean[bg] = (float)mean;
    d_rstd[bg] = rsqrtf((float)var + 1e-5f);
}

// ============================================================
// Stage 7: normalize + affine + exact GELU
// ============================================================
__global__ void k_gnapply(const float* __restrict__ gamma, const float* __restrict__ beta,
                          float* __restrict__ out) {
    int idx = blockIdx.x*256 + threadIdx.x;
    int fidx = idx * 4;
    int o  = (fidx >> 15) & 255;
    int bg = fidx >> 18;
    float a  = gamma[o] * d_rstd[bg];
    float b2 = beta[o] - d_mean[bg] * a;
    float4 h = ((const float4*)d_H)[idx];
    float v0 = h.x*a + b2, v1 = h.y*a + b2, v2 = h.z*a + b2, v3 = h.w*a + b2;
    float4 r;
    r.x = v0 * normcdff(v0);
    r.y = v1 * normcdff(v1);
    r.z = v2 * normcdff(v2);
    r.w = v3 * normcdff(v3);
    ((float4*)out)[idx] = r;
}

// ============================================================
extern "C" void kernel_launch(void* const* d_in, const int* in_sizes, int n_in,
                              void* d_out, int out_size) {
    const float* x      = (const float*)d_in[0];
    const float* conv_w = (const float*)d_in[1];
    const float* conv_b = (const float*)d_in[2];
    const float* gamma  = (const float*)d_in[3];
    const float* beta   = (const float*)d_in[4];
    const float* wmat   = (const float*)d_in[5];
    const float* pct    = (const float*)d_in[6];
    float* out = (float*)d_out;

    k_fft_fwd     <<<ROWS1/8, 256>>>(x);
    k_buildA      <<<dim3(4,2,MMAX), 256>>>(wmat, pct);
    k_wsplit      <<<256, 256>>>(conv_w);
    k_legendre_mma<<<dim3(8, MMAX), 256>>>();
    k_ifft        <<<ROWS2/8, 256>>>();
    k_ytrans      <<<dim3(HWLO/32, CIN/32, BATCH), 256>>>();
    k_conv_mma    <<<dim3(HWLO/128, COUT/128, BATCH), 256>>>(conv_b);
    k_gnstat1     <<<512, 256>>>();
    k_gnstat2     <<<1, 64>>>();
    k_gnapply     <<<(BC*HWLO)/4/256, 256>>>(gamma, beta, out);
}

// round 5
// speedup vs baseline: 1.4314x; 1.1117x over previous
#include <cuda_runtime.h>
#include <cuda_bf16.h>
#include <math.h>
#include <stdint.h>

#define BATCH 2
#define CIN 256
#define COUT 256
#define HHI 256
#define WHI 512
#define HLO 128
#define WLO 256
#define MMAX 129
#define LMAX 128
#define CPG 8
#define BC (BATCH*CIN)          /* 512    */
#define ROWS1 (BC*HHI)          /* 131072 */
#define ROWS2 (BC*HLO)          /* 65536  */
#define HWLO (HLO*WLO)          /* 32768  */

// -------- scratch (static device globals; no allocation allowed) --------
__device__ __align__(16) __nv_bfloat16 d_Xr_hi[MMAX*ROWS1];
__device__ __align__(16) __nv_bfloat16 d_Xr_lo[MMAX*ROWS1];
__device__ __align__(16) __nv_bfloat16 d_Xi_hi[MMAX*ROWS1];
__device__ __align__(16) __nv_bfloat16 d_Xi_lo[MMAX*ROWS1];
__device__ __align__(16) __nv_bfloat16 d_At_hi[MMAX*HLO*HHI];   // [m][klo][kh]
__device__ __align__(16) __nv_bfloat16 d_At_lo[MMAX*HLO*HHI];
__device__ __align__(16) __nv_bfloat16 d_Whi[COUT*CIN];
__device__ __align__(16) __nv_bfloat16 d_Wlo[COUT*CIN];
__device__ float d_Gr[MMAX*ROWS2];        // [m][bc*128+klo]
__device__ float d_Gi[MMAX*ROWS2];
__device__ float d_Y [BC*HWLO];           // [b][c][hw]
__device__ __align__(16) __nv_bfloat16 d_Yt_hi[BATCH*HWLO*CIN]; // [b][hw][c]
__device__ __align__(16) __nv_bfloat16 d_Yt_lo[BATCH*HWLO*CIN];
__device__ float d_H [BC*HWLO];           // [b][o][hw]
__device__ double d_ps[512], d_ps2[512];
__device__ float d_mean[BATCH*32];
__device__ float d_rstd[BATCH*32];

// ======================= helpers =======================
__device__ __forceinline__ uint32_t smem_u32(const void* p) {
    uint32_t a;
    asm("{ .reg .u64 t; cvta.to.shared.u64 t, %1; cvt.u32.u64 %0, t; }" : "=r"(a) : "l"(p));
    return a;
}
__device__ __forceinline__ void ldsm_x4(uint32_t& r0, uint32_t& r1, uint32_t& r2, uint32_t& r3, uint32_t addr) {
    asm volatile("ldmatrix.sync.aligned.m8n8.x4.shared.b16 {%0,%1,%2,%3}, [%4];"
        : "=r"(r0), "=r"(r1), "=r"(r2), "=r"(r3) : "r"(addr));
}
__device__ __forceinline__ void mma16816(float* d, const uint32_t* a, uint32_t b0, uint32_t b1) {
    asm volatile("mma.sync.aligned.m16n8k16.row.col.f32.bf16.bf16.f32 "
        "{%0,%1,%2,%3}, {%4,%5,%6,%7}, {%8,%9}, {%0,%1,%2,%3};"
        : "+f"(d[0]), "+f"(d[1]), "+f"(d[2]), "+f"(d[3])
        : "r"(a[0]), "r"(a[1]), "r"(a[2]), "r"(a[3]), "r"(b0), "r"(b1));
}
__device__ __forceinline__ void cp16(uint32_t dst, const void* src) {
    asm volatile("cp.async.cg.shared.global [%0], [%1], 16;" :: "r"(dst), "l"(src));
}
__device__ __forceinline__ void split2(float v, __nv_bfloat16& h, __nv_bfloat16& l) {
    h = __float2bfloat16(v);
    l = __float2bfloat16(v - __bfloat162float(h));
}

// ============================================================
// Shared 128x128 GEMM core, K=256, bf16 hi/lo 3-term split, fp32 accum.
// cp.async double-buffered; all 3 terms computed per K-chunk.
// A[128][256] k-major, B[128][256] k-major. D[r][c] += A[r][k]*B[c][k] (+bias[r]).
// 256 threads: warp grid 4(m) x 2(n), warp tile 32x64.
// Dynamic smem: 2 stages x {Ahi,Alo,Bhi,Blo} x 16KB = 128KB.
// ============================================================
#define GEMM_SMEM (2*4*16384)

__device__ __forceinline__ void gemm_core(
    const __nv_bfloat16* __restrict__ Ahi, const __nv_bfloat16* __restrict__ Alo,
    const __nv_bfloat16* __restrict__ Bhi, const __nv_bfloat16* __restrict__ Blo,
    float* __restrict__ D, int ldD, const float* __restrict__ bias, uint32_t sm)
{
    int tid = threadIdx.x;
    int wid = tid >> 5, lane = tid & 31;
    int wm = wid >> 1, wn = wid & 1;

    float acc[2][8][4];
    #pragma unroll
    for (int i=0;i<2;i++)
        #pragma unroll
        for (int j=0;j<8;j++)
            #pragma unroll
            for (int q=0;q<4;q++) acc[i][j][q] = 0.f;

    // issue a chunk's 4 tiles into stage st
    auto load_chunk = [&](int st, int kc) {
        uint32_t base = sm + st*65536;
        #pragma unroll
        for (int e = tid; e < 1024; e += 256) {
            int row = e >> 3, c = e & 7;
            uint32_t off = (uint32_t)(row << 7) + (uint32_t)((c ^ (row & 7)) << 4);
            const size_t g = (size_t)row*256 + kc*64 + c*8;
            cp16(base         + off, Ahi + g);
            cp16(base + 16384 + off, Alo + g);
            cp16(base + 32768 + off, Bhi + g);
            cp16(base + 49152 + off, Blo + g);
        }
        asm volatile("cp.async.commit_group;" ::: "memory");
    };

    load_chunk(0, 0);

    #pragma unroll 1
    for (int kc = 0; kc < 4; kc++) {
        if (kc < 3) {
            load_chunk((kc+1) & 1, kc+1);
            asm volatile("cp.async.wait_group 1;" ::: "memory");
        } else {
            asm volatile("cp.async.wait_group 0;" ::: "memory");
        }
        __syncthreads();

        uint32_t base  = sm + (kc & 1)*65536;
        uint32_t sAhi = base, sAlo = base + 16384, sBhi = base + 32768, sBlo = base + 49152;

        #pragma unroll
        for (int ks = 0; ks < 4; ks++) {
            int c = ks*2 + (lane >> 4);
            uint32_t a_h[2][4], a_l[2][4];
            #pragma unroll
            for (int mi = 0; mi < 2; mi++) {
                int row = wm*32 + mi*16 + (lane & 15);
                uint32_t off = (uint32_t)(row << 7) + (uint32_t)((c ^ (row & 7)) << 4);
                ldsm_x4(a_h[mi][0], a_h[mi][1], a_h[mi][2], a_h[mi][3], sAhi + off);
                ldsm_x4(a_l[mi][0], a_l[mi][1], a_l[mi][2], a_l[mi][3], sAlo + off);
            }
            uint32_t b[4][4];
            #pragma unroll
            for (int nj = 0; nj < 4; nj++) {
                int row = wn*64 + nj*16 + (lane & 7) + ((lane >> 3) & 1)*8;
                uint32_t off = (uint32_t)(row << 7) + (uint32_t)((c ^ (row & 7)) << 4);
                ldsm_x4(b[nj][0], b[nj][1], b[nj][2], b[nj][3], sBhi + off);
            }
            #pragma unroll
            for (int mi = 0; mi < 2; mi++)
                #pragma unroll
                for (int nj = 0; nj < 4; nj++) {
                    mma16816(acc[mi][nj*2],   a_h[mi], b[nj][0], b[nj][2]);
                    mma16816(acc[mi][nj*2+1], a_h[mi], b[nj][1], b[nj][3]);
                }
            #pragma unroll
            for (int mi = 0; mi < 2; mi++)
                #pragma unroll
                for (int nj = 0; nj < 4; nj++) {
                    mma16816(acc[mi][nj*2],   a_l[mi], b[nj][0], b[nj][2]);
                    mma16816(acc[mi][nj*2+1], a_l[mi], b[nj][1], b[nj][3]);
                }
            #pragma unroll
            for (int nj = 0; nj < 4; nj++) {
                int row = wn*64 + nj*16 + (lane & 7) + ((lane >> 3) & 1)*8;
                uint32_t off = (uint32_t)(row << 7) + (uint32_t)((c ^ (row & 7)) << 4);
                ldsm_x4(b[nj][0], b[nj][1], b[nj][2], b[nj][3], sBlo + off);
            }
            #pragma unroll
            for (int mi = 0; mi < 2; mi++)
                #pragma unroll
                for (int nj = 0; nj < 4; nj++) {
                    mma16816(acc[mi][nj*2],   a_h[mi], b[nj][0], b[nj][2]);
                    mma16816(acc[mi][nj*2+1], a_h[mi], b[nj][1], b[nj][3]);
                }
        }
        __syncthreads();
    }

    int g = lane >> 2, tg = lane & 3;
    #pragma unroll
    for (int mi = 0; mi < 2; mi++) {
        int r0 = wm*32 + mi*16 + g;
        float bv0 = bias ? bias[r0]   : 0.f;
        float bv1 = bias ? bias[r0+8] : 0.f;
        #pragma unroll
        for (int nt = 0; nt < 8; nt++) {
            int col = wn*64 + nt*8 + tg*2;
            float2 v0 = make_float2(acc[mi][nt][0] + bv0, acc[mi][nt][1] + bv0);
            float2 v1 = make_float2(acc[mi][nt][2] + bv1, acc[mi][nt][3] + bv1);
            *(float2*)&D[(size_t)r0*ldD + col]     = v0;
            *(float2*)&D[(size_t)(r0+8)*ldD + col] = v1;
        }
    }
}

// ============================================================
// Stage 1: rfft(512) per row, scaled by 2*pi/512. Output bf16 hi/lo, [m][row].
// 512 threads, 16 rows/block -> 32B full-sector transposed stores.
// ============================================================
__global__ void __launch_bounds__(512) k_fft_fwd(const float* __restrict__ x) {
    __shared__ float sre[16][256];
    __shared__ float sim[16][256];
    __shared__ float twr[128], twi[128];
    __shared__ float uer[129], uei[129];
    int tid = threadIdx.x;
    if (tid < 128) { float s,c; sincosf(-6.283185307179586f*(float)tid/256.0f,&s,&c); twr[tid]=c; twi[tid]=s; }
    if (tid < 129) { float s,c; sincosf(-6.283185307179586f*(float)tid/512.0f,&s,&c); uer[tid]=c; uei[tid]=s; }
    __syncthreads();
    int w = tid >> 5, lane = tid & 31;
    int row = blockIdx.x*16 + w;
    const float4* xr4 = (const float4*)(x + (size_t)row*512);
    #pragma unroll
    for (int j = 0; j < 4; j++) {
        float4 v = xr4[lane + 32*j];
        int f  = lane + 32*j;
        int r0 = __brev(2*f)   >> 24;
        int r1 = __brev(2*f+1) >> 24;
        sre[w][r0]=v.x; sim[w][r0]=v.y;
        sre[w][r1]=v.z; sim[w][r1]=v.w;
    }
    __syncwarp();
    for (int st = 0; st < 8; st++) {
        int half = 1 << st;
        int tstep = 128 >> st;
        #pragma unroll 4
        for (int b = lane; b < 128; b += 32) {
            int blk = b >> st;
            int j   = b & (half-1);
            int i0  = (blk << (st+1)) + j;
            int i1  = i0 + half;
            float wr = twr[j*tstep], wi = twi[j*tstep];
            float ur = sre[w][i0], ui = sim[w][i0];
            float vr = sre[w][i1], vi = sim[w][i1];
            float tr = vr*wr - vi*wi, ti = vr*wi + vi*wr;
            sre[w][i0]=ur+tr; sim[w][i0]=ui+ti;
            sre[w][i1]=ur-tr; sim[w][i1]=ui-ti;
        }
        __syncwarp();
    }
    const float SC = 0.012271846303085129f;  // 2*pi/512
    float ro[5], io[5];
    #pragma unroll
    for (int j = 0; j < 5; j++) {
        int k = lane + 32*j;
        if (k <= 128) {
            int km = (256-k) & 255;
            float zr=sre[w][k],  zi= sim[w][k];
            float mr=sre[w][km], mi=-sim[w][km];
            float er=0.5f*(zr+mr), ei=0.5f*(zi+mi);
            float dr=0.5f*(zr-mr), di=0.5f*(zi-mi);
            float pr=di, pi=-dr;
            float wr=uer[k], wi=uei[k];
            float qr=pr*wr-pi*wi, qi=pr*wi+pi*wr;
            ro[j] = (er+qr)*SC;
            io[j] = (ei+qi)*SC;
        }
    }
    __syncthreads();
    float* ore = (float*)sre;   // reuse butterfly smem for [m][row] staging (2064 floats)
    float* oim = (float*)sim;
    #pragma unroll
    for (int j = 0; j < 5; j++) {
        int k = lane + 32*j;
        if (k <= 128) { ore[k*16+w] = ro[j]; oim[k*16+w] = io[j]; }
    }
    __syncthreads();
    int base = blockIdx.x*16;
    for (int idx = tid; idx < 129*16; idx += 512) {
        int m = idx >> 4, r = idx & 15;
        size_t o = (size_t)m*ROWS1 + base + r;
        __nv_bfloat16 h, l;
        split2(ore[idx], h, l); d_Xr_hi[o]=h; d_Xr_lo[o]=l;
        split2(oim[idx], h, l); d_Xi_hi[o]=h; d_Xi_lo[o]=l;
    }
}

// ============================================================
// Stage 2: At[m][klo][kh] = sum_l wmat[m][l][kh]*pct[m][l][klo], bf16 hi/lo.
// ============================================================
__global__ void k_buildA(const float* __restrict__ wmat, const float* __restrict__ pct) {
    int m    = blockIdx.z;
    int kh0  = blockIdx.x * 64;
    int klo0 = blockIdx.y * 64;
    __shared__ float sW[16][65];
    __shared__ float sP[16][64];
    int tid = threadIdx.x;
    int tx = tid & 15, ty = tid >> 4;
    float acc[4][4] = {};
    const float* wbase = wmat + m*LMAX*HHI;
    const float* pbase = pct  + m*LMAX*HLO;
    for (int l0 = 0; l0 < 128; l0 += 16) {
        #pragma unroll
        for (int q = 0; q < 4; q++) {
            int e = tid + q*256;
            int li = e >> 6, ki = e & 63;
            sW[li][ki] = wbase[(l0+li)*HHI + kh0  + ki];
            sP[li][ki] = pbase[(l0+li)*HLO + klo0 + ki];
        }
        __syncthreads();
        #pragma unroll
        for (int l = 0; l < 16; l++) {
            float a[4], b[4];
            #pragma unroll
            for (int i=0;i<4;i++) a[i]=sW[l][ty*4+i];
            #pragma unroll
            for (int j=0;j<4;j++) b[j]=sP[l][tx*4+j];
            #pragma unroll
            for (int i=0;i<4;i++)
                #pragma unroll
                for (int j=0;j<4;j++) acc[i][j] += a[i]*b[j];
        }
        __syncthreads();
    }
    size_t Abase = (size_t)m*(HLO*HHI);
    #pragma unroll
    for (int j=0;j<4;j++) {
        int klo = klo0 + tx*4 + j;
        __nv_bfloat162 ph0, ph1, pl0, pl1;
        __nv_bfloat16 h, l;
        split2(acc[0][j], h, l); ph0.x=h; pl0.x=l;
        split2(acc[1][j], h, l); ph0.y=h; pl0.y=l;
        split2(acc[2][j], h, l); ph1.x=h; pl1.x=l;
        split2(acc[3][j], h, l); ph1.y=h; pl1.y=l;
        size_t o = Abase + (size_t)klo*HHI + kh0 + ty*4;
        *(__nv_bfloat162*)&d_At_hi[o]   = ph0;
        *(__nv_bfloat162*)&d_At_hi[o+2] = ph1;
        *(__nv_bfloat162*)&d_At_lo[o]   = pl0;
        *(__nv_bfloat162*)&d_At_lo[o+2] = pl1;
    }
}

// ============================================================
// Stage 2b: split conv weights to bf16 hi/lo
// ============================================================
__global__ void k_wsplit(const float* __restrict__ w) {
    int i = blockIdx.x*256 + threadIdx.x;   // 65536 total
    __nv_bfloat16 h, l;
    split2(w[i], h, l);
    d_Whi[i] = h; d_Wlo[i] = l;
}

// ============================================================
// Stage 3: Legendre per-m GEMM via mma.sync.
// blockIdx.x in 0..7: [0..3]=real bc-tiles, [4..7]=imag bc-tiles. blockIdx.y = m.
// ============================================================
__global__ void __launch_bounds__(256) k_legendre_mma() {
    extern __shared__ __align__(128) char dsm[];
    int m = blockIdx.y;
    int bx = blockIdx.x;
    int half = bx >> 2;
    int bc0  = (bx & 3) * 128;
    size_t xo = (size_t)m*ROWS1 + (size_t)bc0*HHI;
    const __nv_bfloat16 *Ah, *Al;
    float* D;
    if (half) { Ah = d_Xi_hi + xo; Al = d_Xi_lo + xo; D = d_Gi; }
    else      { Ah = d_Xr_hi + xo; Al = d_Xr_lo + xo; D = d_Gr; }
    D += (size_t)m*ROWS2 + (size_t)bc0*HLO;
    const __nv_bfloat16* Bh = d_At_hi + (size_t)m*(HLO*HHI);
    const __nv_bfloat16* Bl = d_At_lo + (size_t)m*(HLO*HHI);
    gemm_core(Ah, Al, Bh, Bl, D, HLO, nullptr, smem_u32(dsm));
}

// ============================================================
// Stage 4: irfft(n=256)*256 per row (packed 128-pt inverse FFT).
// ============================================================
__global__ void k_ifft() {
    __shared__ float gre[129*8], gim[129*8];
    __shared__ float sre[8][128], sim[8][128];
    __shared__ float wqr[128], wqi[128];
    __shared__ float t2r[64],  t2i[64];
    int tid = threadIdx.x;
    if (tid < 128){ float s,c; sincosf(6.283185307179586f*(float)tid/256.f,&s,&c); wqr[tid]=c; wqi[tid]=s; }
    if (tid < 64 ){ float s,c; sincosf(6.283185307179586f*(float)tid/128.f,&s,&c); t2r[tid]=c; t2i[tid]=s; }
    int base = blockIdx.x*8;
    for (int idx = tid; idx < 129*8; idx += 256) {
        int m = idx >> 3, r = idx & 7;
        gre[idx] = d_Gr[m*ROWS2 + base + r];
        gim[idx] = d_Gi[m*ROWS2 + base + r];
    }
    __syncthreads();
    int w = tid >> 5, lane = tid & 31;
    #pragma unroll 4
    for (int k = lane; k < 128; k += 32) {
        float ar = gre[k*8+w],        ai =  gim[k*8+w];
        float br = gre[(128-k)*8+w],  bi = -gim[(128-k)*8+w];
        float wr = wqr[k], wi = wqi[k];
        float c1r = 1.f - wi, c1i =  wr;
        float c2r = 1.f + wi, c2i = -wr;
        float Zr = ar*c1r - ai*c1i + br*c2r - bi*c2i;
        float Zi = ar*c1i + ai*c1r + br*c2i + bi*c2r;
        int rv = __brev(k) >> 25;
        sre[w][rv] = Zr; sim[w][rv] = Zi;
    }
    __syncwarp();
    for (int st = 0; st < 7; st++) {
        int half = 1 << st;
        int tstep = 64 >> st;
        #pragma unroll 2
        for (int b = lane; b < 64; b += 32) {
            int blk = b >> st;
            int j   = b & (half-1);
            int i0  = (blk << (st+1)) + j;
            int i1  = i0 + half;
            float wr = t2r[j*tstep], wi = t2i[j*tstep];
            float ur = sre[w][i0], ui = sim[w][i0];
            float vr = sre[w][i1], vi = sim[w][i1];
            float tr = vr*wr - vi*wi, ti = vr*wi + vi*wr;
            sre[w][i0]=ur+tr; sim[w][i0]=ui+ti;
            sre[w][i1]=ur-tr; sim[w][i1]=ui-ti;
        }
        __syncwarp();
    }
    float2* yo = (float2*)d_Y + (size_t)(base + w)*128;
    #pragma unroll 4
    for (int n = lane; n < 128; n += 32)
        yo[n] = make_float2(sre[w][n], sim[w][n]);
}

// ============================================================
// Stage 4b: transpose Y [b][c][hw] -> Yt [b][hw][c] with bf16 split.
// ============================================================
__global__ void k_ytrans() {
    __shared__ float t[32][33];
    int b = blockIdx.z, c0 = blockIdx.y*32, hw0 = blockIdx.x*32;
    int tx = threadIdx.x & 31, ty = threadIdx.x >> 5;   // 256 threads: ty 0..7
    const float* Y = d_Y + (size_t)b*CIN*HWLO;
    #pragma unroll
    for (int q = 0; q < 4; q++) {
        int c = c0 + ty + q*8;
        t[ty + q*8][tx] = Y[(size_t)c*HWLO + hw0 + tx];
    }
    __syncthreads();
    #pragma unroll
    for (int q = 0; q < 4; q++) {
        int hw = hw0 + ty + q*8;
        float v = t[tx][ty + q*8];
        __nv_bfloat16 h, l; split2(v, h, l);
        size_t o = ((size_t)b*HWLO + hw)*CIN + c0 + tx;
        d_Yt_hi[o] = h; d_Yt_lo[o] = l;
    }
}

// ============================================================
// Stage 5: 1x1 conv via mma.sync. D[o][hw] = W[o][c] * Yt[hw][c]
// ============================================================
__global__ void __launch_bounds__(256) k_conv_mma(const float* __restrict__ bias) {
    extern __shared__ __align__(128) char dsm[];
    int b = blockIdx.z, o0 = blockIdx.y*128, hw0 = blockIdx.x*128;
    const __nv_bfloat16* Ah = d_Whi + (size_t)o0*CIN;
    const __nv_bfloat16* Al = d_Wlo + (size_t)o0*CIN;
    const __nv_bfloat16* Bh = d_Yt_hi + ((size_t)b*HWLO + hw0)*CIN;
    const __nv_bfloat16* Bl = d_Yt_lo + ((size_t)b*HWLO + hw0)*CIN;
    float* D = d_H + ((size_t)b*COUT + o0)*HWLO + hw0;
    gemm_core(Ah, Al, Bh, Bl, D, HWLO, bias + o0, smem_u32(dsm));
}

// ============================================================
// Stage 6: GroupNorm stats — two-phase deterministic reduction.
// ============================================================
__global__ void k_gnstat1() {
    int blk = blockIdx.x;             // 512 = 64 groups * 8 parts
    int bg = blk >> 3, part = blk & 7;
    const float* hb = d_H + (size_t)bg*(CPG*HWLO) + part*32768;
    double s = 0.0, s2 = 0.0;
    for (int i = threadIdx.x; i < 32768; i += 256) {
        float v = hb[i];
        s += (double)v; s2 += (double)v*(double)v;
    }
    __shared__ double sh[256], sh2[256];
    sh[threadIdx.x] = s; sh2[threadIdx.x] = s2;
    __syncthreads();
    for (int st = 128; st > 0; st >>= 1) {
        if (threadIdx.x < st) { sh[threadIdx.x] += sh[threadIdx.x+st]; sh2[threadIdx.x] += sh2[threadIdx.x+st]; }
        __syncthreads();
    }
    if (threadIdx.x == 0) { d_ps[blk] = sh[0]; d_ps2[blk] = sh2[0]; }
}
__global__ void k_gnstat2() {
    int bg = threadIdx.x;             // 64 threads
    double s = 0.0, s2 = 0.0;
    #pragma unroll
    for (int p = 0; p < 8; p++) { s += d_ps[bg*8+p]; s2 += d_ps2[bg*8+p]; }
    const double N = (double)(CPG*HWLO);
    double mean = s / N;
    double var  = s2 / N - mean*mean;
    d_mean[bg] = (float)mean;
    d_rstd[bg] = rsqrtf((float)var + 1e-5f);
}

// ============================================================
// Stage 7: normalize + affine + exact GELU
// ============================================================
__global__ void k_gnapply(const float* __restrict__ gamma, const float* __restrict__ beta,
                          float* __restrict__ out) {
    int idx = blockIdx.x*256 + threadIdx.x;
    int fidx = idx * 4;
    int o  = (fidx >> 15) & 255;
    int bg = fidx >> 18;
    float a  = gamma[o] * d_rstd[bg];
    float b2 = beta[o] - d_mean[bg] * a;
    float4 h = ((const float4*)d_H)[idx];
    float v0 = h.x*a + b2, v1 = h.y*a + b2, v2 = h.z*a + b2, v3 = h.w*a + b2;
    float4 r;
    r.x = v0 * normcdff(v0);
    r.y = v1 * normcdff(v1);
    r.z = v2 * normcdff(v2);
    r.w = v3 * normcdff(v3);
    ((float4*)out)[idx] = r;
}

// ============================================================
extern "C" void kernel_launch(void* const* d_in, const int* in_sizes, int n_in,
                              void* d_out, int out_size) {
    const float* x      = (const float*)d_in[0];
    const float* conv_w = (const float*)d_in[1];
    const float* conv_b = (const float*)d_in[2];
    const float* gamma  = (const float*)d_in[3];
    const float* beta   = (const float*)d_in[4];
    const float* wmat   = (const float*)d_in[5];
    const float* pct    = (const float*)d_in[6];
    float* out = (float*)d_out;

    static int attr_done = 0;
    if (!attr_done) {
        cudaFuncSetAttribute(k_legendre_mma, cudaFuncAttributeMaxDynamicSharedMemorySize, GEMM_SMEM);
        cudaFuncSetAttribute(k_conv_mma,     cudaFuncAttributeMaxDynamicSharedMemorySize, GEMM_SMEM);
        attr_done = 1;
    }

    k_fft_fwd     <<<ROWS1/16, 512>>>(x);
    k_buildA      <<<dim3(4,2,MMAX), 256>>>(wmat, pct);
    k_wsplit      <<<256, 256>>>(conv_w);
    k_legendre_mma<<<dim3(8, MMAX), 256, GEMM_SMEM>>>();
    k_ifft        <<<ROWS2/8, 256>>>();
    k_ytrans      <<<dim3(HWLO/32, CIN/32, BATCH), 256>>>();
    k_conv_mma    <<<dim3(HWLO/128, COUT/128, BATCH), 256, GEMM_SMEM>>>(conv_b);
    k_gnstat1     <<<512, 256>>>();
    k_gnstat2     <<<1, 64>>>();
    k_gnapply     <<<(BC*HWLO)/4/256, 256>>>(gamma, beta, out);
}